// round 1
// baseline (speedup 1.0000x reference)
#include <cuda_runtime.h>

// Problem constants
#define BATCH   8
#define NP1     1024   // N+1 tokens
#define DP1     128    // d+1
#define NLAYER  4
#define NHEAD   8
#define NTOK    1023   // N (rows contributing to Gram; divisor)
#define DSMALL  127

// ---------------------------------------------------------------------------
// __device__ scratch (no allocations allowed)
// g_PB[l][h][j][c] = Pfull[c][j]   (P transposed, padded; corner Pfull[127][127]=1)
// g_QT[l][h][k][i] = Qfull[i][k]   (Q transposed, zero padded)
// g_G [b][j][k]    = Gram matrix  Z'^T Z'  (symmetric)
// g_R [b][j][i]    = (1/N) * sum_h Qfull_h G_b Pfull_h^T
// ---------------------------------------------------------------------------
__device__ __align__(16) float g_PB[NLAYER][NHEAD][DP1][DP1];
__device__ __align__(16) float g_QT[NLAYER][NHEAD][DP1][DP1];
__device__ __align__(16) float g_G[BATCH][DP1][DP1];
__device__ __align__(16) float g_R[BATCH][DP1][DP1];

// ---------------------------------------------------------------------------
// Build padded/transposed parameter matrices for all layers/heads.
// allparam layout: [L][H][2][127][127], s=0 -> P, s=1 -> Q.
// ---------------------------------------------------------------------------
__global__ void pad_params_kernel(const float* __restrict__ allparam) {
    int idx = blockIdx.x * blockDim.x + threadIdx.x;
    const int total = NLAYER * NHEAD * DP1 * DP1;
    if (idx >= total) return;
    int bb = idx & 127;          // second index of Pfull/Qfull (fast)
    int a  = (idx >> 7) & 127;   // first smem index
    int h  = (idx >> 14) & 7;
    int l  = idx >> 17;

    float pv = 0.0f, qv = 0.0f;
    if (bb < DSMALL && a < DSMALL) {
        const float* base = allparam
            + ((((size_t)l * NHEAD + h) * 2 + 0) * DSMALL + bb) * DSMALL + a;
        pv = base[0];                         // P[bb][a]
        qv = base[DSMALL * DSMALL];           // Q[bb][a]
    }
    if (bb == DSMALL && a == DSMALL) pv = 1.0f;   // Pfull corner

    // g_PB[l][h][a][bb] = Pfull[bb][a];  g_QT[l][h][a][bb] = Qfull[bb][a]
    g_PB[l][h][a][bb] = pv;
    g_QT[l][h][a][bb] = qv;
}

__global__ void zero_GR_kernel() {
    int idx = blockIdx.x * blockDim.x + threadIdx.x;
    if (idx < BATCH * DP1 * DP1) {
        (&g_G[0][0][0])[idx] = 0.0f;
        (&g_R[0][0][0])[idx] = 0.0f;
    }
}

// ---------------------------------------------------------------------------
// Gram kernel: g_G[b] += Zchunk^T Zchunk over rows [s*64, s*64+64) ∩ [0,1023)
// grid (BATCH, 16), block 256. Each thread: 8x8 microtile of the 128x128 out.
// ---------------------------------------------------------------------------
__global__ void gram_kernel(const float* __restrict__ Z) {
    const int b = blockIdx.x, s = blockIdx.y;
    const int tid = threadIdx.x;
    const int tx = tid & 15, ty = tid >> 4;

    __shared__ __align__(16) float Zs[16][128];

    float acc[8][8];
#pragma unroll
    for (int i = 0; i < 8; i++)
#pragma unroll
        for (int j = 0; j < 8; j++) acc[i][j] = 0.0f;

    const float* Zb = Z + (size_t)b * NP1 * DP1;
    const int m0 = s * 64;

    for (int t = 0; t < 4; t++) {
        const int mt = m0 + t * 16;
        // load 16 rows x 128 cols = 512 float4, 2 per thread (zero beyond row 1022)
#pragma unroll
        for (int q = 0; q < 2; q++) {
            int f = tid + q * 256;         // 0..511
            int row = f >> 5;              // 0..15
            int c4  = f & 31;              // 0..31
            int m = mt + row;
            float4 v = make_float4(0.f, 0.f, 0.f, 0.f);
            if (m < NTOK) v = *(const float4*)&Zb[(size_t)m * DP1 + c4 * 4];
            *(float4*)&Zs[row][c4 * 4] = v;
        }
        __syncthreads();
#pragma unroll
        for (int kk = 0; kk < 16; kk++) {
            float a_[8], b_[8];
            float4 a0 = *(const float4*)&Zs[kk][ty * 8];
            float4 a1 = *(const float4*)&Zs[kk][ty * 8 + 4];
            float4 b0 = *(const float4*)&Zs[kk][tx * 8];
            float4 b1 = *(const float4*)&Zs[kk][tx * 8 + 4];
            a_[0]=a0.x; a_[1]=a0.y; a_[2]=a0.z; a_[3]=a0.w;
            a_[4]=a1.x; a_[5]=a1.y; a_[6]=a1.z; a_[7]=a1.w;
            b_[0]=b0.x; b_[1]=b0.y; b_[2]=b0.z; b_[3]=b0.w;
            b_[4]=b1.x; b_[5]=b1.y; b_[6]=b1.z; b_[7]=b1.w;
#pragma unroll
            for (int i = 0; i < 8; i++)
#pragma unroll
                for (int j = 0; j < 8; j++) acc[i][j] = fmaf(a_[i], b_[j], acc[i][j]);
        }
        __syncthreads();
    }

    float* Gb = &g_G[b][0][0];
#pragma unroll
    for (int i = 0; i < 8; i++)
#pragma unroll
        for (int j = 0; j < 8; j++)
            atomicAdd(&Gb[(ty * 8 + i) * DP1 + tx * 8 + j], acc[i][j]);
}

// ---------------------------------------------------------------------------
// BR kernel: per (b, h, s):  T = G_b @ Pfull_h^T (cols [s*64, s*64+64)) in smem,
// then g_R[b][:, cols] += (1/N) * Qfull_h @ T.
// grid (BATCH, NHEAD, 2), block 256. Microtile 8x4 over 128x64 output.
// ---------------------------------------------------------------------------
__global__ void br_kernel(int layer) {
    const int b = blockIdx.x, h = blockIdx.y, s = blockIdx.z;
    const int colbase = s * 64;
    const int tid = threadIdx.x;
    const int tx = tid & 15, ty = tid >> 4;

    __shared__ __align__(16) float Ts[128][68];
    __shared__ __align__(16) float As[16][128];
    __shared__ __align__(16) float Bs[16][64];

    const float* Gb = &g_G[b][0][0];
    const float* PB = &g_PB[layer][h][0][0];
    const float* QT = &g_QT[layer][h][0][0];

    float acc[8][4];
#pragma unroll
    for (int i = 0; i < 8; i++)
#pragma unroll
        for (int j = 0; j < 4; j++) acc[i][j] = 0.0f;

    // ---- Phase 1: T[k][lc] = sum_j G[k][j] * Pfull[colbase+lc][j] ----
    // As[jj][k] = G[j0+jj][k]  (valid via symmetry of G)
    // Bs[jj][lc] = PB[j0+jj][colbase+lc]
    for (int j0 = 0; j0 < DP1; j0 += 16) {
#pragma unroll
        for (int q = 0; q < 2; q++) {
            int f = tid + q * 256;
            int row = f >> 5, c4 = f & 31;
            *(float4*)&As[row][c4 * 4] = *(const float4*)&Gb[(j0 + row) * DP1 + c4 * 4];
        }
        {
            int row = tid >> 4, c4 = tid & 15;
            *(float4*)&Bs[row][c4 * 4] =
                *(const float4*)&PB[(j0 + row) * DP1 + colbase + c4 * 4];
        }
        __syncthreads();
#pragma unroll
        for (int kk = 0; kk < 16; kk++) {
            float a_[8];
            float4 a0 = *(const float4*)&As[kk][ty * 8];
            float4 a1 = *(const float4*)&As[kk][ty * 8 + 4];
            a_[0]=a0.x; a_[1]=a0.y; a_[2]=a0.z; a_[3]=a0.w;
            a_[4]=a1.x; a_[5]=a1.y; a_[6]=a1.z; a_[7]=a1.w;
            float4 b0 = *(const float4*)&Bs[kk][tx * 4];
            float b_[4] = {b0.x, b0.y, b0.z, b0.w};
#pragma unroll
            for (int i = 0; i < 8; i++)
#pragma unroll
                for (int j = 0; j < 4; j++) acc[i][j] = fmaf(a_[i], b_[j], acc[i][j]);
        }
        __syncthreads();
    }
#pragma unroll
    for (int i = 0; i < 8; i++)
#pragma unroll
        for (int j = 0; j < 4; j++) Ts[ty * 8 + i][tx * 4 + j] = acc[i][j];
    __syncthreads();

    // ---- Phase 2: Racc[i][lc] = sum_k Qfull[i][k] * Ts[k][lc] ----
    // As[kk][i] = QT[k0+kk][i] = Qfull[i][k0+kk]
#pragma unroll
    for (int i = 0; i < 8; i++)
#pragma unroll
        for (int j = 0; j < 4; j++) acc[i][j] = 0.0f;

    for (int k0 = 0; k0 < DP1; k0 += 16) {
#pragma unroll
        for (int q = 0; q < 2; q++) {
            int f = tid + q * 256;
            int row = f >> 5, c4 = f & 31;
            *(float4*)&As[row][c4 * 4] = *(const float4*)&QT[(k0 + row) * DP1 + c4 * 4];
        }
        __syncthreads();
#pragma unroll
        for (int kk = 0; kk < 16; kk++) {
            float a_[8];
            float4 a0 = *(const float4*)&As[kk][ty * 8];
            float4 a1 = *(const float4*)&As[kk][ty * 8 + 4];
            a_[0]=a0.x; a_[1]=a0.y; a_[2]=a0.z; a_[3]=a0.w;
            a_[4]=a1.x; a_[5]=a1.y; a_[6]=a1.z; a_[7]=a1.w;
            float4 b0 = *(const float4*)&Ts[k0 + kk][tx * 4];
            float b_[4] = {b0.x, b0.y, b0.z, b0.w};
#pragma unroll
            for (int i = 0; i < 8; i++)
#pragma unroll
                for (int j = 0; j < 4; j++) acc[i][j] = fmaf(a_[i], b_[j], acc[i][j]);
        }
        __syncthreads();
    }

    const float invN = 1.0f / (float)NTOK;
    float* Rb = &g_R[b][0][0];
#pragma unroll
    for (int i = 0; i < 8; i++)
#pragma unroll
        for (int j = 0; j < 4; j++)
            atomicAdd(&Rb[(ty * 8 + i) * DP1 + colbase + tx * 4 + j],
                      acc[i][j] * invN);
}

// ---------------------------------------------------------------------------
// Update kernel: Z[b, n0:n0+128, :] += Z[b, n0:n0+128, :] @ g_R[b]   (in place;
// each block owns its rows exclusively, so RAW is contained within the block)
// grid (BATCH, 8), block 256, microtile 8x8.
// ---------------------------------------------------------------------------
__global__ void update_kernel(float* __restrict__ Z) {
    const int b = blockIdx.x, nt = blockIdx.y;
    const int n0 = nt * 128;
    const int tid = threadIdx.x;
    const int tx = tid & 15, ty = tid >> 4;

    __shared__ __align__(16) float As[16][132];   // transposed Z staging (padded)
    __shared__ __align__(16) float Bs[16][128];

    float* Zb = Z + (size_t)b * NP1 * DP1;
    const float* Rb = &g_R[b][0][0];

    float acc[8][8];
#pragma unroll
    for (int i = 0; i < 8; i++)
#pragma unroll
        for (int j = 0; j < 8; j++) acc[i][j] = 0.0f;

    for (int k0 = 0; k0 < DP1; k0 += 16) {
        // As[kk][row] = Zb[(n0+row)*128 + k0+kk]   (transpose-on-store)
#pragma unroll
        for (int q = 0; q < 2; q++) {
            int f = tid + q * 256;     // 0..511
            int row = f >> 2;          // 0..127
            int kq  = f & 3;           // 0..3
            float4 v = *(const float4*)&Zb[(size_t)(n0 + row) * DP1 + k0 + kq * 4];
            As[kq * 4 + 0][row] = v.x;
            As[kq * 4 + 1][row] = v.y;
            As[kq * 4 + 2][row] = v.z;
            As[kq * 4 + 3][row] = v.w;
        }
        // Bs[kk][j] = Rb[(k0+kk)*128 + j]
#pragma unroll
        for (int q = 0; q < 2; q++) {
            int f = tid + q * 256;
            int row = f >> 5, c4 = f & 31;
            *(float4*)&Bs[row][c4 * 4] = *(const float4*)&Rb[(k0 + row) * DP1 + c4 * 4];
        }
        __syncthreads();
#pragma unroll
        for (int kk = 0; kk < 16; kk++) {
            float a_[8], b_[8];
#pragma unroll
            for (int i = 0; i < 8; i++) a_[i] = As[kk][ty * 8 + i];
            float4 b0 = *(const float4*)&Bs[kk][tx * 8];
            float4 b1 = *(const float4*)&Bs[kk][tx * 8 + 4];
            b_[0]=b0.x; b_[1]=b0.y; b_[2]=b0.z; b_[3]=b0.w;
            b_[4]=b1.x; b_[5]=b1.y; b_[6]=b1.z; b_[7]=b1.w;
#pragma unroll
            for (int i = 0; i < 8; i++)
#pragma unroll
                for (int j = 0; j < 8; j++) acc[i][j] = fmaf(a_[i], b_[j], acc[i][j]);
        }
        __syncthreads();
    }

    // Residual add, in place (each thread touches only its own elements)
#pragma unroll
    for (int i = 0; i < 8; i++) {
        int r = n0 + ty * 8 + i;
        float4* p = (float4*)&Zb[(size_t)r * DP1 + tx * 8];
        float4 o0 = p[0], o1 = p[1];
        o0.x += acc[i][0]; o0.y += acc[i][1]; o0.z += acc[i][2]; o0.w += acc[i][3];
        o1.x += acc[i][4]; o1.y += acc[i][5]; o1.z += acc[i][6]; o1.w += acc[i][7];
        p[0] = o0; p[1] = o1;
    }
}

// ---------------------------------------------------------------------------
extern "C" void kernel_launch(void* const* d_in, const int* in_sizes, int n_in,
                              void* d_out, int out_size) {
    const float* Z_in     = (const float*)d_in[0];
    const float* allparam = (const float*)d_in[1];
    float* Z = (float*)d_out;

    cudaMemcpyAsync(Z, Z_in, sizeof(float) * BATCH * NP1 * DP1,
                    cudaMemcpyDeviceToDevice);

    pad_params_kernel<<<(NLAYER * NHEAD * DP1 * DP1 + 255) / 256, 256>>>(allparam);

    for (int l = 0; l < NLAYER; l++) {
        zero_GR_kernel<<<(BATCH * DP1 * DP1 + 255) / 256, 256>>>();
        gram_kernel<<<dim3(BATCH, 16), 256>>>(Z);
        br_kernel<<<dim3(BATCH, NHEAD, 2), 256>>>(l);
        update_kernel<<<dim3(BATCH, 8), 256>>>(Z);
    }
}

// round 4
// speedup vs baseline: 2.2673x; 2.2673x over previous
#include <cuda_runtime.h>

// Problem constants
#define BATCH   8
#define NP1     1024
#define DP1     128
#define NLAYER  4
#define NHEAD   8
#define NTOK    1023
#define DSMALL  127

// ---------------------------------------------------------------------------
// Scratch (static __device__; no allocations allowed)
// g_PB[l][h][a][b] = Pfull[b][a]   (P^T, padded; corner Pfull[127][127]=1)
// g_QT[l][h][k][i] = Qfull[i][k]   (Q^T, zero padded)
// g_G  [b]  : Gram (symmetric), updated per layer via G <- (I+R)^T G (I+R)
// g_Gt [b]  : Gtmp = G (I+R)
// g_R  [b]  : R_l = (1/N) sum_h Q_h G P_h^T
// g_W[2][b] : W = M^T ping-pong, M = prod_l (I+R_l);  W_{l+1} = (I+R_l)^T W_l
// g_T[b][h] : T_h = G P_h^T
// ---------------------------------------------------------------------------
__device__ __align__(16) float g_PB[NLAYER][NHEAD][DP1][DP1];
__device__ __align__(16) float g_QT[NLAYER][NHEAD][DP1][DP1];
__device__ __align__(16) float g_G [BATCH][DP1][DP1];
__device__ __align__(16) float g_Gt[BATCH][DP1][DP1];
__device__ __align__(16) float g_R [BATCH][DP1][DP1];
__device__ __align__(16) float g_W [2][BATCH][DP1][DP1];
__device__ __align__(16) float g_T [BATCH][NHEAD][DP1][DP1];

// ---------------------------------------------------------------------------
__global__ void pad_params_kernel(const float* __restrict__ allparam) {
    int idx = blockIdx.x * blockDim.x + threadIdx.x;
    const int total = NLAYER * NHEAD * DP1 * DP1;
    if (idx >= total) return;
    int bb = idx & 127;
    int a  = (idx >> 7) & 127;
    int h  = (idx >> 14) & 7;
    int l  = idx >> 17;

    float pv = 0.0f, qv = 0.0f;
    if (bb < DSMALL && a < DSMALL) {
        const float* base = allparam
            + ((((size_t)l * NHEAD + h) * 2 + 0) * DSMALL + bb) * DSMALL + a;
        pv = base[0];
        qv = base[DSMALL * DSMALL];
    }
    if (bb == DSMALL && a == DSMALL) pv = 1.0f;

    g_PB[l][h][a][bb] = pv;
    g_QT[l][h][a][bb] = qv;
}

__global__ void init_kernel() {
    int idx = blockIdx.x * blockDim.x + threadIdx.x;   // < 8*128*128
    int j = idx & 127, i = (idx >> 7) & 127, b = idx >> 14;
    g_G[b][i][j] = 0.0f;
    g_W[0][b][i][j] = (i == j) ? 1.0f : 0.0f;
}

// ---------------------------------------------------------------------------
// Gram: G[b] += Zslab^T Zslab over rows [s*64, s*64+64) ∩ [0,1023)
// grid (8,16), 256 thr. One smem load (64x128), ONE sync, 8x8 microtile.
// ---------------------------------------------------------------------------
__global__ __launch_bounds__(256) void gram_kernel(const float* __restrict__ Z) {
    const int b = blockIdx.x, s = blockIdx.y;
    const int tid = threadIdx.x, tx = tid & 15, ty = tid >> 4;
    __shared__ __align__(16) float Zs[64][DP1];

    const float* Zb = Z + (size_t)b * NP1 * DP1;
    const int m0 = s * 64;
#pragma unroll
    for (int q = 0; q < 8; q++) {
        int f = tid + q * 256;
        int row = f >> 5, c4 = f & 31;
        int m = m0 + row;
        float4 v = make_float4(0.f, 0.f, 0.f, 0.f);
        if (m < NTOK) v = *(const float4*)&Zb[(size_t)m * DP1 + c4 * 4];
        *(float4*)&Zs[row][c4 * 4] = v;
    }
    __syncthreads();

    float acc[8][8];
#pragma unroll
    for (int i = 0; i < 8; i++)
#pragma unroll
        for (int j = 0; j < 8; j++) acc[i][j] = 0.0f;

#pragma unroll 8
    for (int kk = 0; kk < 64; kk++) {
        float4 a0 = *(const float4*)&Zs[kk][ty * 8];
        float4 a1 = *(const float4*)&Zs[kk][ty * 8 + 4];
        float4 b0 = *(const float4*)&Zs[kk][tx * 8];
        float4 b1 = *(const float4*)&Zs[kk][tx * 8 + 4];
        float a_[8] = {a0.x, a0.y, a0.z, a0.w, a1.x, a1.y, a1.z, a1.w};
        float b_[8] = {b0.x, b0.y, b0.z, b0.w, b1.x, b1.y, b1.z, b1.w};
#pragma unroll
        for (int i = 0; i < 8; i++)
#pragma unroll
            for (int j = 0; j < 8; j++) acc[i][j] = fmaf(a_[i], b_[j], acc[i][j]);
    }

    float* Gb = &g_G[b][0][0];
#pragma unroll
    for (int i = 0; i < 8; i++)
#pragma unroll
        for (int j = 0; j < 8; j++)
            atomicAdd(&Gb[(ty * 8 + i) * DP1 + tx * 8 + j], acc[i][j]);
}

// ---------------------------------------------------------------------------
// T kernel: T[b][h] = G[b] @ Pfull_h^T (col slice). grid (8,8,2), 256 thr.
// Output tile 128x64, 8x4 microtile. Double-buffered smem, reg-staged LDG.
// Uses symmetry of G for transpose-free A staging. h==0 blocks zero g_R.
// ---------------------------------------------------------------------------
__global__ __launch_bounds__(256) void t_kernel(int layer) {
    const int b = blockIdx.x, h = blockIdx.y, s = blockIdx.z;
    const int tid = threadIdx.x, tx = tid & 15, ty = tid >> 4;
    const int c0 = s * 64;
    __shared__ __align__(16) float As[2][16][DP1];
    __shared__ __align__(16) float Bs[2][16][64];

    const float* Gb = &g_G[b][0][0];
    const float* PB = &g_PB[layer][h][0][0];

    const int ar = tid >> 5, ac = (tid & 31) * 4;    // A stage coords (rows ar, ar+8)
    const int br = tid >> 4, bc = (tid & 15) * 4;    // B stage coords

    float4 ra0, ra1, rb;
    // preload chunk 0
    ra0 = *(const float4*)&Gb[(0 + ar) * DP1 + ac];
    ra1 = *(const float4*)&Gb[(8 + ar) * DP1 + ac];
    rb  = *(const float4*)&PB[(0 + br) * DP1 + c0 + bc];
    *(float4*)&As[0][ar][ac] = ra0;
    *(float4*)&As[0][ar + 8][ac] = ra1;
    *(float4*)&Bs[0][br][bc] = rb;
    __syncthreads();

    float acc[8][4];
#pragma unroll
    for (int i = 0; i < 8; i++)
#pragma unroll
        for (int j = 0; j < 4; j++) acc[i][j] = 0.0f;

    for (int t = 0; t < 8; t++) {
        const int cur = t & 1;
        if (t < 7) {
            int j0 = (t + 1) * 16;
            ra0 = *(const float4*)&Gb[(j0 + ar) * DP1 + ac];
            ra1 = *(const float4*)&Gb[(j0 + 8 + ar) * DP1 + ac];
            rb  = *(const float4*)&PB[(j0 + br) * DP1 + c0 + bc];
        }
#pragma unroll
        for (int kk = 0; kk < 16; kk++) {
            float4 a0 = *(const float4*)&As[cur][kk][ty * 8];
            float4 a1 = *(const float4*)&As[cur][kk][ty * 8 + 4];
            float4 bv = *(const float4*)&Bs[cur][kk][tx * 4];
            float a_[8] = {a0.x, a0.y, a0.z, a0.w, a1.x, a1.y, a1.z, a1.w};
            float b_[4] = {bv.x, bv.y, bv.z, bv.w};
#pragma unroll
            for (int i = 0; i < 8; i++)
#pragma unroll
                for (int j = 0; j < 4; j++) acc[i][j] = fmaf(a_[i], b_[j], acc[i][j]);
        }
        if (t < 7) {
            const int nxt = cur ^ 1;
            *(float4*)&As[nxt][ar][ac] = ra0;
            *(float4*)&As[nxt][ar + 8][ac] = ra1;
            *(float4*)&Bs[nxt][br][bc] = rb;
            __syncthreads();
        }
    }

    float* Tb = &g_T[b][h][0][0];
#pragma unroll
    for (int i = 0; i < 8; i++) {
        float4 v = make_float4(acc[i][0], acc[i][1], acc[i][2], acc[i][3]);
        *(float4*)&Tb[(ty * 8 + i) * DP1 + c0 + tx * 4] = v;
    }
    if (h == 0) {
        float4 z4 = make_float4(0.f, 0.f, 0.f, 0.f);
        float* Rb = &g_R[b][0][0];
#pragma unroll
        for (int i = 0; i < 8; i++)
            *(float4*)&Rb[(ty * 8 + i) * DP1 + c0 + tx * 4] = z4;
    }
}

// ---------------------------------------------------------------------------
// R kernel: R[b] += (1/N) Q_h @ T[b][h] (col slice). grid (8,8,2), 256 thr.
// Same shape as t_kernel; atomic accumulate over h.
// ---------------------------------------------------------------------------
__global__ __launch_bounds__(256) void r_kernel(int layer) {
    const int b = blockIdx.x, h = blockIdx.y, s = blockIdx.z;
    const int tid = threadIdx.x, tx = tid & 15, ty = tid >> 4;
    const int c0 = s * 64;
    __shared__ __align__(16) float As[2][16][DP1];
    __shared__ __align__(16) float Bs[2][16][64];

    const float* QT = &g_QT[layer][h][0][0];
    const float* Tb = &g_T[b][h][0][0];

    const int ar = tid >> 5, ac = (tid & 31) * 4;
    const int br = tid >> 4, bc = (tid & 15) * 4;

    float4 ra0, ra1, rb;
    ra0 = *(const float4*)&QT[(0 + ar) * DP1 + ac];
    ra1 = *(const float4*)&QT[(8 + ar) * DP1 + ac];
    rb  = *(const float4*)&Tb[(0 + br) * DP1 + c0 + bc];
    *(float4*)&As[0][ar][ac] = ra0;
    *(float4*)&As[0][ar + 8][ac] = ra1;
    *(float4*)&Bs[0][br][bc] = rb;
    __syncthreads();

    float acc[8][4];
#pragma unroll
    for (int i = 0; i < 8; i++)
#pragma unroll
        for (int j = 0; j < 4; j++) acc[i][j] = 0.0f;

    for (int t = 0; t < 8; t++) {
        const int cur = t & 1;
        if (t < 7) {
            int k0 = (t + 1) * 16;
            ra0 = *(const float4*)&QT[(k0 + ar) * DP1 + ac];
            ra1 = *(const float4*)&QT[(k0 + 8 + ar) * DP1 + ac];
            rb  = *(const float4*)&Tb[(k0 + br) * DP1 + c0 + bc];
        }
#pragma unroll
        for (int kk = 0; kk < 16; kk++) {
            float4 a0 = *(const float4*)&As[cur][kk][ty * 8];
            float4 a1 = *(const float4*)&As[cur][kk][ty * 8 + 4];
            float4 bv = *(const float4*)&Bs[cur][kk][tx * 4];
            float a_[8] = {a0.x, a0.y, a0.z, a0.w, a1.x, a1.y, a1.z, a1.w};
            float b_[4] = {bv.x, bv.y, bv.z, bv.w};
#pragma unroll
            for (int i = 0; i < 8; i++)
#pragma unroll
                for (int j = 0; j < 4; j++) acc[i][j] = fmaf(a_[i], b_[j], acc[i][j]);
        }
        if (t < 7) {
            const int nxt = cur ^ 1;
            *(float4*)&As[nxt][ar][ac] = ra0;
            *(float4*)&As[nxt][ar + 8][ac] = ra1;
            *(float4*)&Bs[nxt][br][bc] = rb;
            __syncthreads();
        }
    }

    const float invN = 1.0f / (float)NTOK;
    float* Rb = &g_R[b][0][0];
#pragma unroll
    for (int i = 0; i < 8; i++)
#pragma unroll
        for (int j = 0; j < 4; j++)
            atomicAdd(&Rb[(ty * 8 + i) * DP1 + c0 + tx * 4 + j], acc[i][j] * invN);
}

// ---------------------------------------------------------------------------
// c1: op0: Gtmp = G + G@R  (uses G symmetry for A staging)
//     op1: Wnew = Wp + R^T@Wp
// grid (8,8): by -> op(1b) | rowtile(1b) | coltile(1b). 64x64 tile, 4x4 micro.
// ---------------------------------------------------------------------------
__global__ __launch_bounds__(256) void c1_kernel(int p) {
    const int b = blockIdx.x, d = blockIdx.y;
    const int op = d >> 2, rt = (d >> 1) & 1, ct = d & 1;
    const int i0 = rt * 64, c0 = ct * 64;
    const int tid = threadIdx.x, tx = tid & 15, ty = tid >> 4;
    __shared__ __align__(16) float As[2][16][64];
    __shared__ __align__(16) float Bs[2][16][64];

    const float* srcA = op ? &g_R[b][0][0] : &g_G[b][0][0];
    const float* srcB = op ? &g_W[p][b][0][0] : &g_R[b][0][0];
    const float* base = op ? &g_W[p][b][0][0] : &g_G[b][0][0];
    float* dst = op ? &g_W[p ^ 1][b][0][0] : &g_Gt[b][0][0];

    const int sr = tid >> 4, sc = (tid & 15) * 4;

    float4 ra, rb;
    ra = *(const float4*)&srcA[(0 + sr) * DP1 + i0 + sc];
    rb = *(const float4*)&srcB[(0 + sr) * DP1 + c0 + sc];
    *(float4*)&As[0][sr][sc] = ra;
    *(float4*)&Bs[0][sr][sc] = rb;
    __syncthreads();

    float acc[4][4];
#pragma unroll
    for (int i = 0; i < 4; i++)
#pragma unroll
        for (int j = 0; j < 4; j++) acc[i][j] = 0.0f;

    for (int t = 0; t < 8; t++) {
        const int cur = t & 1;
        if (t < 7) {
            int k0 = (t + 1) * 16;
            ra = *(const float4*)&srcA[(k0 + sr) * DP1 + i0 + sc];
            rb = *(const float4*)&srcB[(k0 + sr) * DP1 + c0 + sc];
        }
#pragma unroll
        for (int kk = 0; kk < 16; kk++) {
            float4 av = *(const float4*)&As[cur][kk][ty * 4];
            float4 bv = *(const float4*)&Bs[cur][kk][tx * 4];
            float a_[4] = {av.x, av.y, av.z, av.w};
            float b_[4] = {bv.x, bv.y, bv.z, bv.w};
#pragma unroll
            for (int i = 0; i < 4; i++)
#pragma unroll
                for (int j = 0; j < 4; j++) acc[i][j] = fmaf(a_[i], b_[j], acc[i][j]);
        }
        if (t < 7) {
            const int nxt = cur ^ 1;
            *(float4*)&As[nxt][sr][sc] = ra;
            *(float4*)&Bs[nxt][sr][sc] = rb;
            __syncthreads();
        }
    }

#pragma unroll
    for (int i = 0; i < 4; i++) {
        int row = i0 + ty * 4 + i;
        float4 b4 = *(const float4*)&base[row * DP1 + c0 + tx * 4];
        float4 v = make_float4(b4.x + acc[i][0], b4.y + acc[i][1],
                               b4.z + acc[i][2], b4.w + acc[i][3]);
        *(float4*)&dst[row * DP1 + c0 + tx * 4] = v;
    }
}

// ---------------------------------------------------------------------------
// c2: G = Gtmp + R^T @ Gtmp.  grid (8,4): by -> rowtile | coltile.
// ---------------------------------------------------------------------------
__global__ __launch_bounds__(256) void c2_kernel() {
    const int b = blockIdx.x, d = blockIdx.y;
    const int rt = d >> 1, ct = d & 1;
    const int i0 = rt * 64, c0 = ct * 64;
    const int tid = threadIdx.x, tx = tid & 15, ty = tid >> 4;
    __shared__ __align__(16) float As[2][16][64];
    __shared__ __align__(16) float Bs[2][16][64];

    const float* srcA = &g_R[b][0][0];
    const float* srcB = &g_Gt[b][0][0];

    const int sr = tid >> 4, sc = (tid & 15) * 4;

    float4 ra, rb;
    ra = *(const float4*)&srcA[(0 + sr) * DP1 + i0 + sc];
    rb = *(const float4*)&srcB[(0 + sr) * DP1 + c0 + sc];
    *(float4*)&As[0][sr][sc] = ra;
    *(float4*)&Bs[0][sr][sc] = rb;
    __syncthreads();

    float acc[4][4];
#pragma unroll
    for (int i = 0; i < 4; i++)
#pragma unroll
        for (int j = 0; j < 4; j++) acc[i][j] = 0.0f;

    for (int t = 0; t < 8; t++) {
        const int cur = t & 1;
        if (t < 7) {
            int k0 = (t + 1) * 16;
            ra = *(const float4*)&srcA[(k0 + sr) * DP1 + i0 + sc];
            rb = *(const float4*)&srcB[(k0 + sr) * DP1 + c0 + sc];
        }
#pragma unroll
        for (int kk = 0; kk < 16; kk++) {
            float4 av = *(const float4*)&As[cur][kk][ty * 4];
            float4 bv = *(const float4*)&Bs[cur][kk][tx * 4];
            float a_[4] = {av.x, av.y, av.z, av.w};
            float b_[4] = {bv.x, bv.y, bv.z, bv.w};
#pragma unroll
            for (int i = 0; i < 4; i++)
#pragma unroll
                for (int j = 0; j < 4; j++) acc[i][j] = fmaf(a_[i], b_[j], acc[i][j]);
        }
        if (t < 7) {
            const int nxt = cur ^ 1;
            *(float4*)&As[nxt][sr][sc] = ra;
            *(float4*)&Bs[nxt][sr][sc] = rb;
            __syncthreads();
        }
    }

    float* Gb = &g_G[b][0][0];
    const float* Gt = &g_Gt[b][0][0];
#pragma unroll
    for (int i = 0; i < 4; i++) {
        int row = i0 + ty * 4 + i;
        float4 b4 = *(const float4*)&Gt[row * DP1 + c0 + tx * 4];
        float4 v = make_float4(b4.x + acc[i][0], b4.y + acc[i][1],
                               b4.z + acc[i][2], b4.w + acc[i][3]);
        *(float4*)&Gb[row * DP1 + c0 + tx * 4] = v;
    }
}

// ---------------------------------------------------------------------------
// Final: Zout = Zin @ W^T  (W = M^T includes identity; M = prod_l (I+R_l)).
// grid (8,16): 64-row tiles, full 128 cols. 4x8 microtile, double-buffered.
// Both A (Zin chunk) and B (W^T chunk) are transpose-staged.
// ---------------------------------------------------------------------------
__global__ __launch_bounds__(256) void final_kernel(const float* __restrict__ Zin,
                                                    float* __restrict__ Zout) {
    const int b = blockIdx.x, rt = blockIdx.y;
    const int n0 = rt * 64;
    const int tid = threadIdx.x, tx = tid & 15, ty = tid >> 4;
    __shared__ __align__(16) float As[2][16][68];
    __shared__ __align__(16) float Bs[2][16][132];

    const float* Zb = Zin + (size_t)b * NP1 * DP1;
    float* Zo = Zout + (size_t)b * NP1 * DP1;
    const float* Wb = &g_W[0][b][0][0];

    const int arow = tid >> 2, aq = tid & 3;         // A: 64 rows x 4 float4
    const int brow0 = tid >> 2, bq = tid & 3;        // B: 128 rows x 4 float4 (x2)

    float4 va, vb0, vb1;
    va  = *(const float4*)&Zb[(size_t)(n0 + arow) * DP1 + aq * 4];
    vb0 = *(const float4*)&Wb[brow0 * DP1 + bq * 4];
    vb1 = *(const float4*)&Wb[(brow0 + 64) * DP1 + bq * 4];
    {
        As[0][aq * 4 + 0][arow] = va.x;  As[0][aq * 4 + 1][arow] = va.y;
        As[0][aq * 4 + 2][arow] = va.z;  As[0][aq * 4 + 3][arow] = va.w;
        Bs[0][bq * 4 + 0][brow0] = vb0.x; Bs[0][bq * 4 + 1][brow0] = vb0.y;
        Bs[0][bq * 4 + 2][brow0] = vb0.z; Bs[0][bq * 4 + 3][brow0] = vb0.w;
        Bs[0][bq * 4 + 0][brow0 + 64] = vb1.x; Bs[0][bq * 4 + 1][brow0 + 64] = vb1.y;
        Bs[0][bq * 4 + 2][brow0 + 64] = vb1.z; Bs[0][bq * 4 + 3][brow0 + 64] = vb1.w;
    }
    __syncthreads();

    float acc[4][8];
#pragma unroll
    for (int i = 0; i < 4; i++)
#pragma unroll
        for (int j = 0; j < 8; j++) acc[i][j] = 0.0f;

    for (int t = 0; t < 8; t++) {
        const int cur = t & 1;
        if (t < 7) {
            int k0 = (t + 1) * 16;
            va  = *(const float4*)&Zb[(size_t)(n0 + arow) * DP1 + k0 + aq * 4];
            vb0 = *(const float4*)&Wb[brow0 * DP1 + k0 + bq * 4];
            vb1 = *(const float4*)&Wb[(brow0 + 64) * DP1 + k0 + bq * 4];
        }
#pragma unroll
        for (int kk = 0; kk < 16; kk++) {
            float4 av = *(const float4*)&As[cur][kk][ty * 4];
            float4 b0 = *(const float4*)&Bs[cur][kk][tx * 8];
            float4 b1 = *(const float4*)&Bs[cur][kk][tx * 8 + 4];
            float a_[4] = {av.x, av.y, av.z, av.w};
            float b_[8] = {b0.x, b0.y, b0.z, b0.w, b1.x, b1.y, b1.z, b1.w};
#pragma unroll
            for (int i = 0; i < 4; i++)
#pragma unroll
                for (int j = 0; j < 8; j++) acc[i][j] = fmaf(a_[i], b_[j], acc[i][j]);
        }
        if (t < 7) {
            const int nxt = cur ^ 1;
            As[nxt][aq * 4 + 0][arow] = va.x;  As[nxt][aq * 4 + 1][arow] = va.y;
            As[nxt][aq * 4 + 2][arow] = va.z;  As[nxt][aq * 4 + 3][arow] = va.w;
            Bs[nxt][bq * 4 + 0][brow0] = vb0.x; Bs[nxt][bq * 4 + 1][brow0] = vb0.y;
            Bs[nxt][bq * 4 + 2][brow0] = vb0.z; Bs[nxt][bq * 4 + 3][brow0] = vb0.w;
            Bs[nxt][bq * 4 + 0][brow0 + 64] = vb1.x; Bs[nxt][bq * 4 + 1][brow0 + 64] = vb1.y;
            Bs[nxt][bq * 4 + 2][brow0 + 64] = vb1.z; Bs[nxt][bq * 4 + 3][brow0 + 64] = vb1.w;
            __syncthreads();
        }
    }

    // Z_out = Z_in @ W^T  (identity already inside W — NO residual add)
#pragma unroll
    for (int i = 0; i < 4; i++) {
        size_t off = (size_t)(n0 + ty * 4 + i) * DP1 + tx * 8;
        float4 o0 = make_float4(acc[i][0], acc[i][1], acc[i][2], acc[i][3]);
        float4 o1 = make_float4(acc[i][4], acc[i][5], acc[i][6], acc[i][7]);
        *(float4*)&Zo[off] = o0;
        *(float4*)&Zo[off + 4] = o1;
    }
}

// ---------------------------------------------------------------------------
extern "C" void kernel_launch(void* const* d_in, const int* in_sizes, int n_in,
                              void* d_out, int out_size) {
    const float* Z_in     = (const float*)d_in[0];
    const float* allparam = (const float*)d_in[1];
    float* Z_out = (float*)d_out;

    pad_params_kernel<<<(NLAYER * NHEAD * DP1 * DP1 + 255) / 256, 256>>>(allparam);
    init_kernel<<<(BATCH * DP1 * DP1 + 255) / 256, 256>>>();
    gram_kernel<<<dim3(BATCH, 16), 256>>>(Z_in);

    for (int l = 0; l < NLAYER; l++) {
        t_kernel<<<dim3(BATCH, NHEAD, 2), 256>>>(l);
        r_kernel<<<dim3(BATCH, NHEAD, 2), 256>>>(l);
        c1_kernel<<<dim3(BATCH, 8), 256>>>(l & 1);
        c2_kernel<<<dim3(BATCH, 4), 256>>>();
    }

    final_kernel<<<dim3(BATCH, 16), 256>>>(Z_in, Z_out);
}